// round 1
// baseline (speedup 1.0000x reference)
#include <cuda_runtime.h>
#include <cuda_bf16.h>
#include <math.h>

// Problem constants
#define BATCH 2
#define SEQ   2048
#define EMBD  1024
#define NHEAD 16
#define HDIM  64
#define BT    (BATCH*SEQ)          // 4096
#define QKVN  (3*EMBD)             // 3072

// ---------------- scratch (device globals; no runtime allocation) ----------------
__device__ float g_qkv[BT * QKVN];                 // [B*T, 3C]
__device__ float g_q[BATCH * NHEAD * SEQ * HDIM];  // [B,H,T,D]
__device__ float g_k[BATCH * NHEAD * SEQ * HDIM];
__device__ float g_v[BATCH * NHEAD * SEQ * HDIM];
__device__ float g_att[BT * EMBD];                 // [B,T,C]

// ---------------- generic SGEMM: C[M,N] = A[M,K] @ B[K,N] + bias[N] ----------------
// BM=BN=128, BK=16, 256 threads, 8x8 microtile. M%128==0, N%128==0, K%16==0 assumed.
__global__ __launch_bounds__(256) void sgemm_bias(
    const float* __restrict__ A, const float* __restrict__ B,
    const float* __restrict__ bias, float* __restrict__ C,
    int M, int N, int K)
{
    __shared__ float As[16][128];   // As[k][m]
    __shared__ float Bs[16][132];   // Bs[k][n] (padded)

    const int tid = threadIdx.x;
    const int ty = tid >> 4;        // 0..15 -> row group
    const int tx = tid & 15;        // 0..15 -> col group
    const int m0 = blockIdx.y * 128;
    const int n0 = blockIdx.x * 128;

    float acc[8][8];
#pragma unroll
    for (int i = 0; i < 8; i++)
#pragma unroll
        for (int j = 0; j < 8; j++) acc[i][j] = 0.f;

    for (int k0 = 0; k0 < K; k0 += 16) {
        // Load A tile 128x16 (as float4), store transposed into As[k][m]
#pragma unroll
        for (int it = 0; it < 2; it++) {
            int idx = tid + it * 256;          // 0..511
            int ar = idx >> 2;                 // 0..127
            int a4 = (idx & 3) << 2;           // 0,4,8,12
            float4 v = *(const float4*)(A + (size_t)(m0 + ar) * K + k0 + a4);
            As[a4 + 0][ar] = v.x;
            As[a4 + 1][ar] = v.y;
            As[a4 + 2][ar] = v.z;
            As[a4 + 3][ar] = v.w;
        }
        // Load B tile 16x128 (as float4), direct
#pragma unroll
        for (int it = 0; it < 2; it++) {
            int idx = tid + it * 256;          // 0..511
            int br = idx >> 5;                 // 0..15
            int b4 = (idx & 31) << 2;          // 0..124
            *(float4*)(&Bs[br][b4]) = *(const float4*)(B + (size_t)(k0 + br) * N + n0 + b4);
        }
        __syncthreads();

#pragma unroll
        for (int kk = 0; kk < 16; kk++) {
            float a[8], b[8];
            *(float4*)(a)     = *(const float4*)(&As[kk][ty * 8]);
            *(float4*)(a + 4) = *(const float4*)(&As[kk][ty * 8 + 4]);
            *(float4*)(b)     = *(const float4*)(&Bs[kk][tx * 8]);
            *(float4*)(b + 4) = *(const float4*)(&Bs[kk][tx * 8 + 4]);
#pragma unroll
            for (int i = 0; i < 8; i++)
#pragma unroll
                for (int j = 0; j < 8; j++)
                    acc[i][j] = fmaf(a[i], b[j], acc[i][j]);
        }
        __syncthreads();
    }

    // Epilogue: add bias, write (vectorized)
#pragma unroll
    for (int i = 0; i < 8; i++) {
        int m = m0 + ty * 8 + i;
        float* crow = C + (size_t)m * N + n0 + tx * 8;
        const float* brow = bias + n0 + tx * 8;
#pragma unroll
        for (int j4 = 0; j4 < 2; j4++) {
            float4 bv = *(const float4*)(brow + j4 * 4);
            float4 o;
            o.x = acc[i][j4 * 4 + 0] + bv.x;
            o.y = acc[i][j4 * 4 + 1] + bv.y;
            o.z = acc[i][j4 * 4 + 2] + bv.z;
            o.w = acc[i][j4 * 4 + 3] + bv.w;
            *(float4*)(crow + j4 * 4) = o;
        }
    }
}

// ---------------- RoPE + transpose/scatter qkv -> q,k,v in [B,H,T,D] ----------------
// one thread per (b,t,h,pair) ; pairs = HDIM/2 = 32
__global__ __launch_bounds__(256) void rope_scatter(
    const float* __restrict__ cosb, const float* __restrict__ sinb)
{
    int idx = blockIdx.x * 256 + threadIdx.x;   // < 2*2048*16*32 = 2^21
    int i = idx & 31;                // pair index 0..31
    int h = (idx >> 5) & 15;
    int t = (idx >> 9) & 2047;
    int b = idx >> 20;

    const float c = cosb[t * 32 + i];
    const float s = sinb[t * 32 + i];

    size_t rowq = ((size_t)(b * SEQ + t)) * QKVN + h * HDIM + 2 * i;
    float2 q = *(const float2*)(g_qkv + rowq);
    float2 k = *(const float2*)(g_qkv + rowq + EMBD);
    float2 v = *(const float2*)(g_qkv + rowq + 2 * EMBD);

    size_t o = (((size_t)(b * NHEAD + h) * SEQ + t)) * HDIM + 2 * i;
    *(float2*)(g_q + o) = make_float2(q.x * c - q.y * s, q.x * s + q.y * c);
    *(float2*)(g_k + o) = make_float2(k.x * c - k.y * s, k.x * s + k.y * c);
    *(float2*)(g_v + o) = v;
}

// ---------------- flash attention, fp32, causal ----------------
// block = 64 queries of one (b,h); 256 threads; iterate 64-key tiles with online softmax.
#define PADW 65
__global__ __launch_bounds__(256) void attn_kernel()
{
    extern __shared__ float sm[];
    float* Qs   = sm;                    // 64*65
    float* Ks   = sm + 64 * PADW;
    float* Vs   = sm + 2 * 64 * PADW;
    float* Ps   = sm + 3 * 64 * PADW;
    float* rowm = sm + 4 * 64 * PADW;    // 64
    float* rowl = rowm + 64;
    float* rowa = rowl + 64;

    const int qt = blockIdx.x;           // query tile
    const int bh = blockIdx.y;           // b*16 + h
    const int b  = bh >> 4;
    const int h  = bh & 15;
    const float* qp = g_q + (size_t)bh * SEQ * HDIM;
    const float* kp = g_k + (size_t)bh * SEQ * HDIM;
    const float* vp = g_v + (size_t)bh * SEQ * HDIM;
    const int q0 = qt * 64;

    const int tid = threadIdx.x;
    const int ty = tid >> 4, tx = tid & 15;

    for (int e = tid; e < 64 * 64; e += 256) {
        int r = e >> 6, c = e & 63;
        Qs[r * PADW + c] = qp[(size_t)(q0 + r) * HDIM + c];
    }
    if (tid < 64) { rowm[tid] = -INFINITY; rowl[tid] = 0.f; }

    float acc[4][4];
#pragma unroll
    for (int i = 0; i < 4; i++)
#pragma unroll
        for (int j = 0; j < 4; j++) acc[i][j] = 0.f;
    __syncthreads();

    for (int kt = 0; kt <= qt; kt++) {
        const int k0 = kt * 64;
        for (int e = tid; e < 64 * 64; e += 256) {
            int r = e >> 6, c = e & 63;
            Ks[r * PADW + c] = kp[(size_t)(k0 + r) * HDIM + c];
            Vs[r * PADW + c] = vp[(size_t)(k0 + r) * HDIM + c];
        }
        __syncthreads();

        // S = Q K^T (4x4 microtile per thread)
        float s[4][4];
#pragma unroll
        for (int i = 0; i < 4; i++)
#pragma unroll
            for (int j = 0; j < 4; j++) s[i][j] = 0.f;

#pragma unroll 8
        for (int d = 0; d < 64; d++) {
            float aq[4], bk[4];
#pragma unroll
            for (int i = 0; i < 4; i++) aq[i] = Qs[(ty * 4 + i) * PADW + d];
#pragma unroll
            for (int j = 0; j < 4; j++) bk[j] = Ks[(tx * 4 + j) * PADW + d];
#pragma unroll
            for (int i = 0; i < 4; i++)
#pragma unroll
                for (int j = 0; j < 4; j++)
                    s[i][j] = fmaf(aq[i], bk[j], s[i][j]);
        }

        const bool diag = (kt == qt);
#pragma unroll
        for (int i = 0; i < 4; i++) {
#pragma unroll
            for (int j = 0; j < 4; j++) {
                float v = s[i][j] * 0.125f;    // 1/sqrt(64)
                if (diag && (k0 + tx * 4 + j) > (q0 + ty * 4 + i)) v = -INFINITY;
                Ps[(ty * 4 + i) * PADW + tx * 4 + j] = v;
            }
        }
        __syncthreads();

        // row-wise online softmax update (8 warps x 8 rows)
        {
            const int w = tid >> 5, lane = tid & 31;
#pragma unroll
            for (int r8 = 0; r8 < 8; r8++) {
                int row = w * 8 + r8;
                float v0 = Ps[row * PADW + lane];
                float v1 = Ps[row * PADW + lane + 32];
                float mx = fmaxf(v0, v1);
#pragma unroll
                for (int o = 16; o; o >>= 1) mx = fmaxf(mx, __shfl_xor_sync(0xffffffffu, mx, o));
                float mold = rowm[row];
                float mnew = fmaxf(mold, mx);
                float p0 = __expf(v0 - mnew);
                float p1 = __expf(v1 - mnew);
                Ps[row * PADW + lane] = p0;
                Ps[row * PADW + lane + 32] = p1;
                float sum = p0 + p1;
#pragma unroll
                for (int o = 16; o; o >>= 1) sum += __shfl_xor_sync(0xffffffffu, sum, o);
                if (lane == 0) {
                    float a = __expf(mold - mnew);
                    rowa[row] = a;
                    rowl[row] = rowl[row] * a + sum;
                    rowm[row] = mnew;
                }
            }
        }
        __syncthreads();

        // rescale accumulators
#pragma unroll
        for (int i = 0; i < 4; i++) {
            float a = rowa[ty * 4 + i];
#pragma unroll
            for (int j = 0; j < 4; j++) acc[i][j] *= a;
        }

        // O += P @ V
#pragma unroll 8
        for (int kk = 0; kk < 64; kk++) {
            float p[4], vv[4];
#pragma unroll
            for (int i = 0; i < 4; i++) p[i] = Ps[(ty * 4 + i) * PADW + kk];
#pragma unroll
            for (int j = 0; j < 4; j++) vv[j] = Vs[kk * PADW + tx * 4 + j];
#pragma unroll
            for (int i = 0; i < 4; i++)
#pragma unroll
                for (int j = 0; j < 4; j++)
                    acc[i][j] = fmaf(p[i], vv[j], acc[i][j]);
        }
        __syncthreads();
    }

    // epilogue: normalize, write to [B,T,C]
#pragma unroll
    for (int i = 0; i < 4; i++) {
        int row = ty * 4 + i;
        float inv = 1.f / rowl[row];
        size_t base = ((size_t)(b * SEQ + q0 + row)) * EMBD + h * HDIM + tx * 4;
#pragma unroll
        for (int j = 0; j < 4; j++)
            g_att[base + j] = acc[i][j] * inv;
    }
}

// ---------------- launcher ----------------
extern "C" void kernel_launch(void* const* d_in, const int* in_sizes, int n_in,
                              void* d_out, int out_size)
{
    const float* x     = (const float*)d_in[0];
    const float* Wqkv  = (const float*)d_in[1];
    const float* bqkv  = (const float*)d_in[2];
    const float* Wproj = (const float*)d_in[3];
    const float* bproj = (const float*)d_in[4];
    const float* cosb  = (const float*)d_in[5];
    const float* sinb  = (const float*)d_in[6];
    float* out = (float*)d_out;

    void *p_qkv = nullptr, *p_att = nullptr;
    cudaGetSymbolAddress(&p_qkv, g_qkv);
    cudaGetSymbolAddress(&p_att, g_att);

    // 1) QKV GEMM: [4096,1024] @ [1024,3072] + bias
    sgemm_bias<<<dim3(QKVN / 128, BT / 128), 256>>>(
        x, Wqkv, bqkv, (float*)p_qkv, BT, QKVN, EMBD);

    // 2) RoPE + transpose to [B,H,T,D]
    rope_scatter<<<(BATCH * SEQ * NHEAD * (HDIM / 2)) / 256, 256>>>(cosb, sinb);

    // 3) causal flash attention
    const int smem_bytes = (4 * 64 * PADW + 3 * 64) * sizeof(float);
    cudaFuncSetAttribute(attn_kernel, cudaFuncAttributeMaxDynamicSharedMemorySize, smem_bytes);
    attn_kernel<<<dim3(SEQ / 64, BATCH * NHEAD), 256, smem_bytes>>>();

    // 4) output projection: [4096,1024] @ [1024,1024] + bias
    sgemm_bias<<<dim3(EMBD / 128, BT / 128), 256>>>(
        (const float*)p_att, Wproj, bproj, out, BT, EMBD, EMBD);
}